// round 1
// baseline (speedup 1.0000x reference)
#include <cuda_runtime.h>

#define BB 4
#define CC 128
#define CQ 16
#define NN 4096
#define TT 64

// ---------------- scratch (no allocations allowed) ----------------
__device__ float g_q[(size_t)BB*NN*CQ];      // [b][n][d]
__device__ float g_k[(size_t)BB*CQ*NN];      // [b][d][n]
__device__ float g_v[(size_t)BB*CC*NN];      // [b][c][n]
__device__ float g_rmax[(size_t)BB*NN];
__device__ float g_rinv[(size_t)BB*NN];

// ---------------- f32x2 helpers (packed dual-FMA) ----------------
static __device__ __forceinline__ unsigned long long pack2(float x, float y) {
    unsigned long long r;
    asm("mov.b64 %0, {%1, %2};" : "=l"(r) : "f"(x), "f"(y));
    return r;
}
static __device__ __forceinline__ void fma2(unsigned long long& d,
                                            unsigned long long a,
                                            unsigned long long b) {
    asm("fma.rn.f32x2 %0, %1, %2, %3;" : "=l"(d) : "l"(a), "l"(b), "l"(d));
}
static __device__ __forceinline__ float2 unpack2(unsigned long long v) {
    float x, y;
    asm("mov.b64 {%0, %1}, %2;" : "=f"(x), "=f"(y) : "l"(v));
    return make_float2(x, y);
}

// ================= kernel 1: q,k,v (1x1 convs as GEMM) =================
// block = (b, 64-position tile). smem: x tile [128][64] + all weights [160][129] + bias.
__global__ __launch_bounds__(256) void qkv_kernel(
    const float* __restrict__ x,
    const float* __restrict__ wq, const float* __restrict__ bq,
    const float* __restrict__ wk, const float* __restrict__ bk,
    const float* __restrict__ wv, const float* __restrict__ bv)
{
    extern __shared__ float sm1[];
    float* xs = sm1;                 // [128][64]
    float* ws = sm1 + CC*TT;         // [160][129] (pad -> conflict-free lane-strided reads)
    float* bs = ws + 160*129;        // [160]

    int bid = blockIdx.x;
    int b = bid & 3, tb = bid >> 2;
    int n0 = tb * TT;
    int t = threadIdx.x;

    for (int idx = t; idx < CC*TT; idx += 256) {
        int c = idx >> 6, j = idx & 63;
        xs[c*TT + j] = x[((size_t)b*CC + c)*NN + n0 + j];
    }
    for (int idx = t; idx < 160*CC; idx += 256) {
        int o = idx >> 7, c = idx & 127;
        float w;
        if (o < CQ)        w = wq[o*CC + c];
        else if (o < 2*CQ) w = wk[(o-CQ)*CC + c];
        else               w = wv[(o-2*CQ)*CC + c];
        ws[o*129 + c] = w;
    }
    if (t < 160) bs[t] = (t < CQ) ? bq[t] : (t < 2*CQ) ? bk[t-CQ] : bv[t-2*CQ];
    __syncthreads();

    int o0 = (t & 31)*5;      // 32 lanes * 5 rows = 160 output rows
    int j0 = (t >> 5)*8;      // 8 warps * 8 cols = 64 positions
    float acc[5][8];
    #pragma unroll
    for (int oo = 0; oo < 5; oo++)
        #pragma unroll
        for (int jj = 0; jj < 8; jj++) acc[oo][jj] = 0.f;

    for (int c = 0; c < CC; c++) {
        float wv5[5];
        #pragma unroll
        for (int oo = 0; oo < 5; oo++) wv5[oo] = ws[(o0+oo)*129 + c];
        float4 xa = *(const float4*)(xs + c*TT + j0);
        float4 xb = *(const float4*)(xs + c*TT + j0 + 4);
        float xv[8] = {xa.x, xa.y, xa.z, xa.w, xb.x, xb.y, xb.z, xb.w};
        #pragma unroll
        for (int oo = 0; oo < 5; oo++)
            #pragma unroll
            for (int jj = 0; jj < 8; jj++)
                acc[oo][jj] += wv5[oo]*xv[jj];
    }

    #pragma unroll
    for (int oo = 0; oo < 5; oo++) {
        int o = o0 + oo;
        float bias = bs[o];
        #pragma unroll
        for (int jj = 0; jj < 8; jj++) {
            int n = n0 + j0 + jj;
            float v = acc[oo][jj] + bias;
            if (o < CQ)        g_q[((size_t)b*NN + n)*CQ + o] = v;
            else if (o < 2*CQ) g_k[((size_t)b*CQ + (o-CQ))*NN + n] = v;
            else               g_v[((size_t)b*CC + (o-2*CQ))*NN + n] = v;
        }
    }
}

// ================= kernel 2: per-row softmax stats =================
// block = (b, row-block r). 64 rows share k tiles. Online (max,sum) per thread,
// then shfl-combine across the 4 threads covering each row.
__global__ __launch_bounds__(256) void stats_kernel() {
    __shared__ float ks[CQ*TT];
    int bid = blockIdx.x;
    int b = bid & 3, r = 63 - (bid >> 2);    // biggest blocks first
    int n0 = r*TT;
    int ntile = r + 1;
    int t = threadIdx.x;
    int pi = t >> 2, pj0 = (t & 3) << 4;

    float qr[CQ];
    const float* qp = g_q + ((size_t)b*NN + n0 + pi)*CQ;
    #pragma unroll
    for (int d = 0; d < CQ; d += 4) {
        float4 q4 = *(const float4*)(qp + d);
        qr[d] = q4.x; qr[d+1] = q4.y; qr[d+2] = q4.z; qr[d+3] = q4.w;
    }

    float mval = -1e30f, sval = 0.f;
    for (int ti = 0; ti < ntile; ti++) {
        int m0 = ti*TT;
        __syncthreads();
        for (int idx = t; idx < CQ*TT; idx += 256) {
            int d = idx >> 6, j = idx & 63;
            ks[d*TT + j] = g_k[((size_t)b*CQ + d)*NN + m0 + j];
        }
        __syncthreads();
        float e[16];
        #pragma unroll
        for (int jj = 0; jj < 16; jj++) {
            float a = 0.f;
            #pragma unroll
            for (int d = 0; d < CQ; d++) a += qr[d]*ks[d*TT + pj0 + jj];
            e[jj] = a;
        }
        float tmax = e[0];
        #pragma unroll
        for (int jj = 1; jj < 16; jj++) tmax = fmaxf(tmax, e[jj]);
        float mnew = fmaxf(mval, tmax);
        float ts = 0.f;
        #pragma unroll
        for (int jj = 0; jj < 16; jj++) ts += __expf(e[jj] - mnew);
        sval = sval*__expf(mval - mnew) + ts;
        mval = mnew;
    }
    #pragma unroll
    for (int off = 1; off <= 2; off <<= 1) {
        float mo = __shfl_xor_sync(0xffffffffu, mval, off);
        float so = __shfl_xor_sync(0xffffffffu, sval, off);
        float mn = fmaxf(mval, mo);
        sval = sval*__expf(mval - mn) + so*__expf(mo - mn);
        mval = mn;
    }
    if ((t & 3) == 0) {
        g_rmax[(size_t)b*NN + n0 + pi] = mval;
        g_rinv[(size_t)b*NN + n0 + pi] = 1.f/sval;
    }
}

// ================= kernel 3: attention write + out = gamma*V.P^T + x =================
// block = (b, row-block r), 64-row x 64-col tiles over valid columns.
// Phase A: e -> p, STG p (coalesced) + stash p in smem [j][i].
// Phase B: f32x2 FFMA microtile (4c x 8i per thread), smem reads are
//          row-broadcasts (j warp-uniform) -> conflict-free.
__global__ __launch_bounds__(256) void attn_kernel(
    const float* __restrict__ x, const float* __restrict__ gamma,
    float* __restrict__ outp, float* __restrict__ attnp)
{
    extern __shared__ float sm3[];
    float* ks = sm3;                 // [16][64]
    float* vs = sm3 + CQ*TT;         // [64][132] = [j][c], pad kills transpose-STS conflicts
    float* ps = vs + TT*132;         // [64][64]  = [j][i]

    int bid = blockIdx.x;
    int b = bid & 3, r = 63 - (bid >> 2);
    int n0 = r*TT;
    int ntile = r + 1;
    int M = ntile*TT;
    int t = threadIdx.x;
    int pi = t >> 2, pj0 = (t & 3) << 4;     // phase-A mapping
    int c0 = (t & 31) << 2, i0 = (t >> 5) << 3;  // phase-B mapping

    float qr[CQ];
    const float* qp = g_q + ((size_t)b*NN + n0 + pi)*CQ;
    #pragma unroll
    for (int d = 0; d < CQ; d += 4) {
        float4 q4 = *(const float4*)(qp + d);
        qr[d] = q4.x; qr[d+1] = q4.y; qr[d+2] = q4.z; qr[d+3] = q4.w;
    }
    float rmax = g_rmax[(size_t)b*NN + n0 + pi];
    float rinv = g_rinv[(size_t)b*NN + n0 + pi];
    float* arow = attnp + ((size_t)b*NN + n0 + pi)*NN;

    unsigned long long acc2[16];     // [cc][ipair]
    #pragma unroll
    for (int i = 0; i < 16; i++) acc2[i] = 0ull;

    for (int ti = 0; ti < ntile; ti++) {
        int m0 = ti*TT;
        __syncthreads();
        for (int idx = t; idx < CQ*TT; idx += 256) {
            int d = idx >> 6, j = idx & 63;
            ks[d*TT + j] = g_k[((size_t)b*CQ + d)*NN + m0 + j];
        }
        for (int idx = t; idx < CC*TT; idx += 256) {
            int c = idx >> 6, j = idx & 63;
            vs[j*132 + c] = g_v[((size_t)b*CC + c)*NN + m0 + j];
        }
        __syncthreads();

        // ---- phase A: p tile + attention store ----
        #pragma unroll
        for (int g4 = 0; g4 < 4; g4++) {
            float pv[4];
            #pragma unroll
            for (int jj = 0; jj < 4; jj++) {
                int j = pj0 + g4*4 + jj;
                float e = 0.f;
                #pragma unroll
                for (int d = 0; d < CQ; d++) e += qr[d]*ks[d*TT + j];
                float p = __expf(e - rmax)*rinv;
                pv[jj] = p;
                ps[j*TT + pi] = p;
            }
            *(float4*)(arow + m0 + pj0 + g4*4) =
                make_float4(pv[0], pv[1], pv[2], pv[3]);
        }
        __syncthreads();

        // ---- phase B: acc += V . P^T (f32x2) ----
        for (int j = 0; j < TT; j++) {
            float4 vv = *(const float4*)(vs + j*132 + c0);
            ulonglong2 pq0 = *(const ulonglong2*)(ps + j*TT + i0);
            ulonglong2 pq1 = *(const ulonglong2*)(ps + j*TT + i0 + 4);
            float va[4] = {vv.x, vv.y, vv.z, vv.w};
            #pragma unroll
            for (int cc = 0; cc < 4; cc++) {
                unsigned long long vp = pack2(va[cc], va[cc]);
                fma2(acc2[cc*4+0], vp, pq0.x);
                fma2(acc2[cc*4+1], vp, pq0.y);
                fma2(acc2[cc*4+2], vp, pq1.x);
                fma2(acc2[cc*4+3], vp, pq1.y);
            }
        }
    }

    // ---- zero the masked attention region (exact softmax zeros) ----
    int rem4 = (NN - M) >> 2;
    if (rem4 > 0) {
        float4 z = make_float4(0.f, 0.f, 0.f, 0.f);
        for (int i = t >> 6; i < TT; i += 4) {
            float4* zr = (float4*)(attnp + ((size_t)b*NN + n0 + i)*NN + M);
            for (int jc = t & 63; jc < rem4; jc += 64)
                zr[jc] = z;
        }
    }

    // ---- epilogue: out = gamma*acc + x ----
    float gm = gamma[0];
    #pragma unroll
    for (int cc = 0; cc < 4; cc++) {
        int c = c0 + cc;
        size_t base = ((size_t)b*CC + c)*NN + n0 + i0;
        const float* xp = x + base;
        float* op = outp + base;
        #pragma unroll
        for (int ip = 0; ip < 4; ip++) {
            float2 a = unpack2(acc2[cc*4 + ip]);
            float2 xv = *(const float2*)(xp + 2*ip);
            *(float2*)(op + 2*ip) = make_float2(gm*a.x + xv.x, gm*a.y + xv.y);
        }
    }
}

// ================= launch =================
extern "C" void kernel_launch(void* const* d_in, const int* in_sizes, int n_in,
                              void* d_out, int out_size)
{
    const float* x     = (const float*)d_in[0];
    const float* wq    = (const float*)d_in[1];
    const float* bq    = (const float*)d_in[2];
    const float* wk    = (const float*)d_in[3];
    const float* bk    = (const float*)d_in[4];
    const float* wv    = (const float*)d_in[5];
    const float* bv    = (const float*)d_in[6];
    const float* gamma = (const float*)d_in[7];

    float* outp  = (float*)d_out;                    // [B,C,W,H] first
    float* attnp = outp + (size_t)BB*CC*NN;          // then [B,N,N]

    const int SM1 = (CC*TT + 160*129 + 160) * 4;     // 115,968 B
    const int SM3 = (CQ*TT + TT*132 + TT*TT) * 4;    // 54,272 B
    cudaFuncSetAttribute(qkv_kernel,  cudaFuncAttributeMaxDynamicSharedMemorySize, SM1);
    cudaFuncSetAttribute(attn_kernel, cudaFuncAttributeMaxDynamicSharedMemorySize, SM3);

    qkv_kernel<<<BB*(NN/TT), 256, SM1>>>(x, wq, bq, wk, bk, wv, bv);
    stats_kernel<<<BB*(NN/TT), 256>>>();
    attn_kernel<<<BB*(NN/TT), 256, SM3>>>(x, gamma, outp, attnp);
}

// round 5
// speedup vs baseline: 1.7492x; 1.7492x over previous
#include <cuda_runtime.h>

#define BB 4
#define CC 128
#define CQ 16
#define NN 4096
#define TT 64
#define CH 16
#define NCOMP 640
#define NZERO 1120

// ---------------- scratch ----------------
__device__ float g_q[(size_t)BB*NN*CQ];      // [b][n][d]
__device__ float g_k[(size_t)BB*CQ*NN];      // [b][d][n]
__device__ float g_v[(size_t)BB*CC*NN];      // [b][c][n]
__device__ float g_sum[(size_t)BB*NN];       // softmax denominators (atomic)

// ---------------- helpers ----------------
static __device__ __forceinline__ unsigned long long pack2(float x, float y) {
    unsigned long long r;
    asm("mov.b64 %0, {%1, %2};" : "=l"(r) : "f"(x), "f"(y));
    return r;
}
static __device__ __forceinline__ void fma2(unsigned long long& d,
                                            unsigned long long a,
                                            unsigned long long b) {
    asm("fma.rn.f32x2 %0, %1, %2, %3;" : "=l"(d) : "l"(a), "l"(b), "l"(d));
}
static __device__ __forceinline__ float2 unpack2(unsigned long long v) {
    float x, y;
    asm("mov.b64 {%0, %1}, %2;" : "=f"(x), "=f"(y) : "l"(v));
    return make_float2(x, y);
}
static __device__ __forceinline__ unsigned f2tf32(float f) {
    unsigned r;
    asm("cvt.rn.tf32.f32 %0, %1;" : "=r"(r) : "f"(f));
    return r;
}
static __device__ __forceinline__ void mma_tf32(float c[4],
                                                const unsigned a[4],
                                                const unsigned b0, const unsigned b1) {
    asm volatile("mma.sync.aligned.m16n8k8.row.col.f32.tf32.tf32.f32 "
        "{%0,%1,%2,%3}, {%4,%5,%6,%7}, {%8,%9}, {%0,%1,%2,%3};"
        : "+f"(c[0]), "+f"(c[1]), "+f"(c[2]), "+f"(c[3])
        : "r"(a[0]), "r"(a[1]), "r"(a[2]), "r"(a[3]), "r"(b0), "r"(b1));
}

// ================= kernel 1: q,k,v + out-init + g_sum zero =================
// 128 blocks: (b, 128-position tile). Weights in smem; x via warp-broadcast LDG.
__global__ __launch_bounds__(256) void qkv_kernel(
    const float* __restrict__ x,
    const float* __restrict__ wq, const float* __restrict__ bq,
    const float* __restrict__ wk, const float* __restrict__ bk,
    const float* __restrict__ wv, const float* __restrict__ bv,
    float* __restrict__ outp)
{
    extern __shared__ float sm1[];
    float* ws = sm1;                 // [160][129]
    float* bs = ws + 160*129;        // [160]

    int bid = blockIdx.x;
    int b = bid & 3, tb = bid >> 2;
    int n0 = tb * 128;
    int t = threadIdx.x;

    if (t < 128) g_sum[bid*128 + t] = 0.f;

    for (int idx = t; idx < 160*CC; idx += 256) {
        int o = idx >> 7, c = idx & 127;
        float w;
        if (o < CQ)        w = wq[o*CC + c];
        else if (o < 2*CQ) w = wk[(o-CQ)*CC + c];
        else               w = wv[(o-2*CQ)*CC + c];
        ws[o*129 + c] = w;
    }
    if (t < 160) bs[t] = (t < CQ) ? bq[t] : (t < 2*CQ) ? bk[t-CQ] : bv[t-2*CQ];

    // out = x (pre-init for atomic accumulation)
    for (int idx = t; idx < 4096; idx += 256) {
        int c = idx >> 5, n4 = (idx & 31) << 2;
        size_t a = ((size_t)b*CC + c)*NN + n0 + n4;
        *(float4*)(outp + a) = *(const float4*)(x + a);
    }
    __syncthreads();

    int o0 = (t & 31)*5;
    int j0 = (t >> 5)*16;
    const float* xb = x + (size_t)b*CC*NN + n0 + j0;

    unsigned long long acc2[5][8];
    #pragma unroll
    for (int oo = 0; oo < 5; oo++)
        #pragma unroll
        for (int q = 0; q < 8; q++) acc2[oo][q] = 0ull;

    #pragma unroll 2
    for (int c = 0; c < CC; c++) {
        ulonglong2 xa = *(const ulonglong2*)(xb + (size_t)c*NN);
        ulonglong2 xc = *(const ulonglong2*)(xb + (size_t)c*NN + 4);
        ulonglong2 xe = *(const ulonglong2*)(xb + (size_t)c*NN + 8);
        ulonglong2 xg = *(const ulonglong2*)(xb + (size_t)c*NN + 12);
        #pragma unroll
        for (int oo = 0; oo < 5; oo++) {
            float w = ws[(o0+oo)*129 + c];
            unsigned long long wp = pack2(w, w);
            fma2(acc2[oo][0], wp, xa.x); fma2(acc2[oo][1], wp, xa.y);
            fma2(acc2[oo][2], wp, xc.x); fma2(acc2[oo][3], wp, xc.y);
            fma2(acc2[oo][4], wp, xe.x); fma2(acc2[oo][5], wp, xe.y);
            fma2(acc2[oo][6], wp, xg.x); fma2(acc2[oo][7], wp, xg.y);
        }
    }

    #pragma unroll
    for (int oo = 0; oo < 5; oo++) {
        int o = o0 + oo;
        float bias = bs[o];
        float v[16];
        #pragma unroll
        for (int q = 0; q < 8; q++) {
            float2 u = unpack2(acc2[oo][q]);
            v[2*q] = u.x + bias; v[2*q+1] = u.y + bias;
        }
        if (o < CQ) {
            #pragma unroll
            for (int jj = 0; jj < 16; jj++)
                g_q[((size_t)b*NN + n0 + j0 + jj)*CQ + o] = v[jj];
        } else {
            float* row = (o < 2*CQ) ? (g_k + ((size_t)b*CQ + (o-CQ))*NN)
                                    : (g_v + ((size_t)b*CC + (o-2*CQ))*NN);
            #pragma unroll
            for (int q4 = 0; q4 < 4; q4++)
                *(float4*)(row + n0 + j0 + 4*q4) =
                    make_float4(v[4*q4], v[4*q4+1], v[4*q4+2], v[4*q4+3]);
        }
    }
}

// ================= kernel 2: chunked sum-exp (max-free softmax) =================
__global__ __launch_bounds__(256) void sumexp_kernel() {
    __shared__ float ksm[CQ*TT];
    int bid = blockIdx.x;
    int b = bid / 160, rem = bid % 160;
    int r = 0;
    for (; r < 64; r++) { int nc = 1 + (r>>4); if (rem < nc) break; rem -= nc; }
    int n0 = r*TT;
    int ct0 = rem*CH;
    int nct = min(CH, r + 1 - ct0);
    int t = threadIdx.x;
    int pi = t >> 2, pj0 = (t & 3) << 4;

    float qr[CQ];
    const float* qp = g_q + ((size_t)b*NN + n0 + pi)*CQ;
    #pragma unroll
    for (int d = 0; d < CQ; d += 4) {
        float4 q4 = *(const float4*)(qp + d);
        qr[d] = q4.x; qr[d+1] = q4.y; qr[d+2] = q4.z; qr[d+3] = q4.w;
    }

    float ssum = 0.f;
    for (int tt = 0; tt < nct; tt++) {
        int m0 = (ct0 + tt)*TT;
        __syncthreads();
        { int d = t >> 4, j4 = (t & 15) << 2;
          *(float4*)(ksm + d*TT + j4) =
              *(const float4*)(g_k + ((size_t)b*CQ + d)*NN + m0 + j4); }
        __syncthreads();

        unsigned long long eacc[8];
        #pragma unroll
        for (int p = 0; p < 8; p++) eacc[p] = 0ull;
        #pragma unroll
        for (int d = 0; d < CQ; d++) {
            unsigned long long qd = pack2(qr[d], qr[d]);
            const ulonglong2* kp = (const ulonglong2*)(ksm + d*TT + pj0);
            ulonglong2 kA = kp[0], kB = kp[1], kC = kp[2], kD = kp[3];
            fma2(eacc[0], qd, kA.x); fma2(eacc[1], qd, kA.y);
            fma2(eacc[2], qd, kB.x); fma2(eacc[3], qd, kB.y);
            fma2(eacc[4], qd, kC.x); fma2(eacc[5], qd, kC.y);
            fma2(eacc[6], qd, kD.x); fma2(eacc[7], qd, kD.y);
        }
        #pragma unroll
        for (int p = 0; p < 8; p++) {
            float2 u = unpack2(eacc[p]);
            ssum += __expf(u.x) + __expf(u.y);
        }
    }
    #pragma unroll
    for (int off = 1; off <= 2; off <<= 1)
        ssum += __shfl_xor_sync(0xffffffffu, ssum, off);
    if ((t & 3) == 0)
        atomicAdd(g_sum + (size_t)b*NN + n0 + pi, ssum);
}

// ================= kernel 3: attention write + HMMA tf32 PV (+zero blocks) ===
// smem floats: [0,8192) af (V frags, 8 warps), [8192,12288) bf (P frags),
//              [12288,13312) ks tile.
__global__ __launch_bounds__(256) void attn_kernel(
    const float* __restrict__ gamma,
    float* __restrict__ outp, float* __restrict__ attnp)
{
    extern __shared__ float smf[];
    float* af = smf;
    float* bf = smf + 8192;
    float* ksm = smf + 12288;

    int bid = blockIdx.x;
    int t = threadIdx.x;

    if (bid >= NCOMP) {                       // ---- zero role ----
        int zi = bid - NCOMP;
        int b = zi / 280, rem = zi % 280;
        int ct = 1;
        for (; ct < 64; ct++) { int np = (ct + 7) >> 3; if (rem < np) break; rem -= np; }
        int r0 = rem * 512;
        int rend = min(r0 + 512, ct * 64);
        float4 z = make_float4(0.f, 0.f, 0.f, 0.f);
        size_t colo = (size_t)ct*64 + (size_t)(t & 15)*4;
        for (int row = r0 + (t >> 4); row < rend; row += 16)
            *(float4*)(attnp + ((size_t)b*NN + row)*NN + colo) = z;
        return;
    }

    int b = bid / 160, rem = bid % 160;
    int r = 0;
    for (; r < 64; r++) { int nc = 1 + (r>>4); if (rem < nc) break; rem -= nc; }
    int n0 = r*TT;
    int ct0 = rem*CH;
    int nct = min(CH, r + 1 - ct0);

    int lane = t & 31, w = t >> 5;
    int pi = t >> 2, pj0 = (t & 3) << 4;

    float qr[CQ];
    const float* qp = g_q + ((size_t)b*NN + n0 + pi)*CQ;
    #pragma unroll
    for (int d = 0; d < CQ; d += 4) {
        float4 q4 = *(const float4*)(qp + d);
        qr[d] = q4.x; qr[d+1] = q4.y; qr[d+2] = q4.z; qr[d+3] = q4.w;
    }
    float rinv = 1.0f / g_sum[(size_t)b*NN + n0 + pi];
    float* arow = attnp + ((size_t)b*NN + n0 + pi)*NN;

    float cacc[8][4];
    #pragma unroll
    for (int nb = 0; nb < 8; nb++)
        #pragma unroll
        for (int q = 0; q < 4; q++) cacc[nb][q] = 0.f;

    int nblo = (pi >> 3) & 1, nbp = pi >> 4;

    for (int tt = 0; tt < nct; tt++) {
        int m0 = (ct0 + tt)*TT;
        __syncthreads();
        // stage K tile
        { int d = t >> 4, j4 = (t & 15) << 2;
          *(float4*)(ksm + d*TT + j4) =
              *(const float4*)(g_k + ((size_t)b*CQ + d)*NN + m0 + j4); }
        // stage V -> A frags (tf32)
        #pragma unroll
        for (int q = 0; q < 8; q++) {
            int idx = t + q*256;              // 0..2047
            int c = idx >> 4, mb = (idx & 15) << 2;
            float4 v4 = *(const float4*)(g_v + ((size_t)b*CC + c)*NN + m0 + mb);
            int wc = c >> 4, rowc = c & 15;
            int ksv = mb >> 3;
            int reg = (rowc >> 3) + ((mb >> 2) & 1)*2;
            unsigned* dst = (unsigned*)(af + wc*1024 + ksv*128 + ((rowc & 7) << 4) + reg);
            dst[0]  = f2tf32(v4.x);
            dst[4]  = f2tf32(v4.y);
            dst[8]  = f2tf32(v4.z);
            dst[12] = f2tf32(v4.w);
        }
        __syncthreads();

        // ---- phase A: energy -> P; STG attention; P -> B frags ----
        unsigned long long eacc[8];
        #pragma unroll
        for (int p = 0; p < 8; p++) eacc[p] = 0ull;
        #pragma unroll
        for (int d = 0; d < CQ; d++) {
            unsigned long long qd = pack2(qr[d], qr[d]);
            const ulonglong2* kp = (const ulonglong2*)(ksm + d*TT + pj0);
            ulonglong2 kA = kp[0], kB = kp[1], kC = kp[2], kD = kp[3];
            fma2(eacc[0], qd, kA.x); fma2(eacc[1], qd, kA.y);
            fma2(eacc[2], qd, kB.x); fma2(eacc[3], qd, kB.y);
            fma2(eacc[4], qd, kC.x); fma2(eacc[5], qd, kC.y);
            fma2(eacc[6], qd, kD.x); fma2(eacc[7], qd, kD.y);
        }
        float pv[16];
        #pragma unroll
        for (int p = 0; p < 8; p++) {
            float2 u = unpack2(eacc[p]);
            pv[2*p]   = __expf(u.x)*rinv;
            pv[2*p+1] = __expf(u.y)*rinv;
        }
        #pragma unroll
        for (int g = 0; g < 4; g++)
            *(float4*)(arow + m0 + pj0 + 4*g) =
                make_float4(pv[4*g], pv[4*g+1], pv[4*g+2], pv[4*g+3]);
        #pragma unroll
        for (int h = 0; h < 2; h++) {
            int ksv = ((t & 3) << 1) + h;
            #pragma unroll
            for (int j = 0; j < 4; j++) {
                int ls = ((pi & 7) << 2) + j;
                int s = (nbp + (ls >> 1)) & 3;
                uint2 u2;
                u2.x = f2tf32(pv[h*8 + j]);
                u2.y = f2tf32(pv[h*8 + j + 4]);
                *(uint2*)(bf + ksv*512 + ls*16 + s*4 + nblo*2) = u2;
            }
        }
        __syncthreads();

        // ---- phase B: cacc += V . P^T via mma.sync tf32 ----
        #pragma unroll
        for (int ksv = 0; ksv < 8; ksv++) {
            uint4 a = *(const uint4*)(af + w*1024 + ksv*128 + lane*4);
            unsigned ar[4] = {a.x, a.y, a.z, a.w};
            #pragma unroll
            for (int np2 = 0; np2 < 4; np2++) {
                int s = (np2 + (lane >> 1)) & 3;
                uint4 bv = *(const uint4*)(bf + ksv*512 + lane*16 + s*4);
                mma_tf32(cacc[2*np2],     ar, bv.x, bv.y);
                mma_tf32(cacc[2*np2 + 1], ar, bv.z, bv.w);
            }
        }
    }

    // ---- epilogue: atomic out accumulation ----
    float gm = gamma[0];
    int rowc = lane >> 2, colb = (lane & 3) << 1;
    #pragma unroll
    for (int nb = 0; nb < 8; nb++) {
        int i = nb*8 + colb;
        size_t a0 = ((size_t)b*CC + w*16 + rowc)*NN + n0 + i;
        atomicAdd(outp + a0,            gm*cacc[nb][0]);
        atomicAdd(outp + a0 + 1,        gm*cacc[nb][1]);
        atomicAdd(outp + a0 + 8*NN,     gm*cacc[nb][2]);
        atomicAdd(outp + a0 + 8*NN + 1, gm*cacc[nb][3]);
    }
}

// ================= launch =================
extern "C" void kernel_launch(void* const* d_in, const int* in_sizes, int n_in,
                              void* d_out, int out_size)
{
    const float* x     = (const float*)d_in[0];
    const float* wq    = (const float*)d_in[1];
    const float* bq    = (const float*)d_in[2];
    const float* wk    = (const float*)d_in[3];
    const float* bk    = (const float*)d_in[4];
    const float* wv    = (const float*)d_in[5];
    const float* bv    = (const float*)d_in[6];
    const float* gamma = (const float*)d_in[7];

    float* outp  = (float*)d_out;
    float* attnp = outp + (size_t)BB*CC*NN;

    const int SM1 = (160*129 + 160) * 4;     // 83,200 B
    const int SM3 = 13312 * 4;               // 53,248 B
    cudaFuncSetAttribute(qkv_kernel,  cudaFuncAttributeMaxDynamicSharedMemorySize, SM1);
    cudaFuncSetAttribute(attn_kernel, cudaFuncAttributeMaxDynamicSharedMemorySize, SM3);

    qkv_kernel<<<BB*(NN/128), 256, SM1>>>(x, wq, bq, wk, bk, wv, bv, outp);
    sumexp_kernel<<<NCOMP, 256>>>();
    attn_kernel<<<NCOMP + NZERO, 256, SM3>>>(gamma, outp, attnp);
}

// round 6
// speedup vs baseline: 1.9936x; 1.1397x over previous
#include <cuda_runtime.h>

#define BB 4
#define CC 128
#define CQ 16
#define NN 4096
#define TT 64
#define CH 16
#define NCOMP 640
#define NZERO 1120
#define NVF 256

// ---------------- scratch ----------------
__device__ float g_q[(size_t)BB*NN*CQ];      // [b][n][d]
__device__ float g_k[(size_t)BB*CQ*NN];      // [b][d][n]
__device__ float g_v[(size_t)BB*CC*NN];      // [b][c][n]
__device__ float g_sum[(size_t)BB*NN];       // softmax denominators (atomic)
__device__ uint4 g_vf[(size_t)BB*64*64*32];  // V tf32 A-fragments [b][mt][wc*8+ksv][lane]

// ---------------- helpers ----------------
static __device__ __forceinline__ unsigned long long pack2(float x, float y) {
    unsigned long long r;
    asm("mov.b64 %0, {%1, %2};" : "=l"(r) : "f"(x), "f"(y));
    return r;
}
static __device__ __forceinline__ void fma2(unsigned long long& d,
                                            unsigned long long a,
                                            unsigned long long b) {
    asm("fma.rn.f32x2 %0, %1, %2, %3;" : "=l"(d) : "l"(a), "l"(b), "l"(d));
}
static __device__ __forceinline__ float2 unpack2(unsigned long long v) {
    float x, y;
    asm("mov.b64 {%0, %1}, %2;" : "=f"(x), "=f"(y) : "l"(v));
    return make_float2(x, y);
}
static __device__ __forceinline__ unsigned f2tf32(float f) {
    unsigned r;
    asm("cvt.rn.tf32.f32 %0, %1;" : "=r"(r) : "f"(f));
    return r;
}
static __device__ __forceinline__ void mma_tf32(float c[4],
                                                const unsigned a[4],
                                                const unsigned b0, const unsigned b1) {
    asm volatile("mma.sync.aligned.m16n8k8.row.col.f32.tf32.tf32.f32 "
        "{%0,%1,%2,%3}, {%4,%5,%6,%7}, {%8,%9}, {%0,%1,%2,%3};"
        : "+f"(c[0]), "+f"(c[1]), "+f"(c[2]), "+f"(c[3])
        : "r"(a[0]), "r"(a[1]), "r"(a[2]), "r"(a[3]), "r"(b0), "r"(b1));
}

// ================= kernel 1: q,k,v + out-init + g_sum zero =================
// 512 blocks: (b, 32-position tile). Weights in smem; x via warp-broadcast LDG.
__global__ __launch_bounds__(256) void qkv_kernel(
    const float* __restrict__ x,
    const float* __restrict__ wq, const float* __restrict__ bq,
    const float* __restrict__ wk, const float* __restrict__ bk,
    const float* __restrict__ wv, const float* __restrict__ bv,
    float* __restrict__ outp)
{
    extern __shared__ float sm1[];
    float* ws = sm1;                 // [160][129]
    float* bs = ws + 160*129;        // [160]

    int bid = blockIdx.x;
    int b = bid & 3, tb = bid >> 2;
    int n0 = tb * 32;
    int t = threadIdx.x;

    if (t < 32) g_sum[bid*32 + t] = 0.f;

    for (int idx = t; idx < 160*CC; idx += 256) {
        int o = idx >> 7, c = idx & 127;
        float w;
        if (o < CQ)        w = wq[o*CC + c];
        else if (o < 2*CQ) w = wk[(o-CQ)*CC + c];
        else               w = wv[(o-2*CQ)*CC + c];
        ws[o*129 + c] = w;
    }
    if (t < 160) bs[t] = (t < CQ) ? bq[t] : (t < 2*CQ) ? bk[t-CQ] : bv[t-2*CQ];

    // out = x (pre-init for atomic accumulation)
    for (int idx = t; idx < 1024; idx += 256) {
        int c = idx >> 3, n4 = (idx & 7) << 2;
        size_t a = ((size_t)b*CC + c)*NN + n0 + n4;
        *(float4*)(outp + a) = *(const float4*)(x + a);
    }
    __syncthreads();

    int o0 = (t & 31)*5;
    int j0 = (t >> 5)*4;
    const float* xb = x + (size_t)b*CC*NN + n0 + j0;

    unsigned long long acc2[5][2];
    #pragma unroll
    for (int oo = 0; oo < 5; oo++) { acc2[oo][0] = 0ull; acc2[oo][1] = 0ull; }

    #pragma unroll 4
    for (int c = 0; c < CC; c++) {
        ulonglong2 xa = *(const ulonglong2*)(xb + (size_t)c*NN);
        #pragma unroll
        for (int oo = 0; oo < 5; oo++) {
            float w = ws[(o0+oo)*129 + c];
            unsigned long long wp = pack2(w, w);
            fma2(acc2[oo][0], wp, xa.x);
            fma2(acc2[oo][1], wp, xa.y);
        }
    }

    #pragma unroll
    for (int oo = 0; oo < 5; oo++) {
        int o = o0 + oo;
        float bias = bs[o];
        float2 u0 = unpack2(acc2[oo][0]);
        float2 u1 = unpack2(acc2[oo][1]);
        float v[4] = {u0.x + bias, u0.y + bias, u1.x + bias, u1.y + bias};
        if (o < CQ) {
            #pragma unroll
            for (int jj = 0; jj < 4; jj++)
                g_q[((size_t)b*NN + n0 + j0 + jj)*CQ + o] = v[jj];
        } else {
            float* row = (o < 2*CQ) ? (g_k + ((size_t)b*CQ + (o-CQ))*NN)
                                    : (g_v + ((size_t)b*CC + (o-2*CQ))*NN);
            *(float4*)(row + n0 + j0) = make_float4(v[0], v[1], v[2], v[3]);
        }
    }
}

// ================= kernel 2: chunked sum-exp (1 sync/tile) + V-frag build ====
__global__ __launch_bounds__(256) void sumexp_kernel() {
    __shared__ float ksm[2*CQ*TT];
    int bid = blockIdx.x;
    int t = threadIdx.x;

    if (bid >= NCOMP) {                      // ---- V fragment build role ----
        int vb = bid - NCOMP;                // vb = b*64 + mt
        int b = vb >> 6;
        int mt = vb & 63;
        int ksv = t >> 5, lane = t & 31;
        int m = mt*64 + ksv*8 + (lane & 3);
        int cb = lane >> 2;
        const float* vp = g_v + (size_t)b*CC*NN;
        #pragma unroll
        for (int wc = 0; wc < 8; wc++) {
            int c = wc*16 + cb;
            uint4 u;
            u.x = f2tf32(vp[(size_t)c*NN + m]);
            u.y = f2tf32(vp[(size_t)(c+8)*NN + m]);
            u.z = f2tf32(vp[(size_t)c*NN + m + 4]);
            u.w = f2tf32(vp[(size_t)(c+8)*NN + m + 4]);
            g_vf[((size_t)vb*64 + wc*8 + ksv)*32 + lane] = u;
        }
        return;
    }

    int b = bid / 160, rem = bid % 160;
    int r = 0;
    for (; r < 64; r++) { int nc = 1 + (r>>4); if (rem < nc) break; rem -= nc; }
    int n0 = r*TT;
    int ct0 = rem*CH;
    int nct = min(CH, r + 1 - ct0);
    int pi = t >> 2, pj0 = (t & 3) << 4;
    int sd = t >> 4, sj4 = (t & 15) << 2;

    float qr[CQ];
    const float* qp = g_q + ((size_t)b*NN + n0 + pi)*CQ;
    #pragma unroll
    for (int d = 0; d < CQ; d += 4) {
        float4 q4 = *(const float4*)(qp + d);
        qr[d] = q4.x; qr[d+1] = q4.y; qr[d+2] = q4.z; qr[d+3] = q4.w;
    }
    const float* krow = g_k + ((size_t)b*CQ + sd)*NN + sj4;

    // prestage tile 0
    *(float4*)(ksm + sd*TT + sj4) = *(const float4*)(krow + ct0*TT);

    float ssum = 0.f;
    for (int tt = 0; tt < nct; tt++) {
        int m0 = (ct0 + tt)*TT;
        __syncthreads();
        bool have = (tt + 1 < nct);
        float4 kreg;
        if (have) kreg = *(const float4*)(krow + m0 + TT);
        const float* ks = ksm + (tt & 1)*1024;

        unsigned long long eacc[8];
        #pragma unroll
        for (int p = 0; p < 8; p++) eacc[p] = 0ull;
        #pragma unroll
        for (int d = 0; d < CQ; d++) {
            unsigned long long qd = pack2(qr[d], qr[d]);
            const ulonglong2* kp = (const ulonglong2*)(ks + d*TT + pj0);
            ulonglong2 kA = kp[0], kB = kp[1], kC = kp[2], kD = kp[3];
            fma2(eacc[0], qd, kA.x); fma2(eacc[1], qd, kA.y);
            fma2(eacc[2], qd, kB.x); fma2(eacc[3], qd, kB.y);
            fma2(eacc[4], qd, kC.x); fma2(eacc[5], qd, kC.y);
            fma2(eacc[6], qd, kD.x); fma2(eacc[7], qd, kD.y);
        }
        #pragma unroll
        for (int p = 0; p < 8; p++) {
            float2 u = unpack2(eacc[p]);
            ssum += __expf(u.x) + __expf(u.y);
        }
        if (have)
            *(float4*)(ksm + ((tt+1) & 1)*1024 + sd*TT + sj4) = kreg;
    }
    #pragma unroll
    for (int off = 1; off <= 2; off <<= 1)
        ssum += __shfl_xor_sync(0xffffffffu, ssum, off);
    if ((t & 3) == 0)
        atomicAdd(g_sum + (size_t)b*NN + n0 + pi, ssum);
}

// ================= kernel 3: attention write + HMMA tf32 PV (+zero blocks) ===
// static smem: ksm double buffer 2x[16][64] + P-frag buffer [4096] = 24KB
__global__ __launch_bounds__(256, 2) void attn_kernel(
    const float* __restrict__ gamma,
    float* __restrict__ outp, float* __restrict__ attnp)
{
    __shared__ float smf[2*1024 + 4096];
    float* bf = smf + 2048;

    int bid = blockIdx.x;
    int t = threadIdx.x;

    if (bid >= NCOMP) {                       // ---- zero role ----
        int zi = bid - NCOMP;
        int b = zi / 280, rem = zi % 280;
        int ct = 1;
        for (; ct < 64; ct++) { int np = (ct + 7) >> 3; if (rem < np) break; rem -= np; }
        int r0 = rem * 512;
        int rend = min(r0 + 512, ct * 64);
        float4 z = make_float4(0.f, 0.f, 0.f, 0.f);
        size_t colo = (size_t)ct*64 + (size_t)(t & 15)*4;
        for (int row = r0 + (t >> 4); row < rend; row += 16)
            *(float4*)(attnp + ((size_t)b*NN + row)*NN + colo) = z;
        return;
    }

    int b = bid / 160, rem = bid % 160;
    int r = 0;
    for (; r < 64; r++) { int nc = 1 + (r>>4); if (rem < nc) break; rem -= nc; }
    int n0 = r*TT;
    int ct0 = rem*CH;
    int nct = min(CH, r + 1 - ct0);

    int lane = t & 31, w = t >> 5;
    int pi = t >> 2, pj0 = (t & 3) << 4;
    int sd = t >> 4, sj4 = (t & 15) << 2;

    float qr[CQ];
    const float* qp = g_q + ((size_t)b*NN + n0 + pi)*CQ;
    #pragma unroll
    for (int d = 0; d < CQ; d += 4) {
        float4 q4 = *(const float4*)(qp + d);
        qr[d] = q4.x; qr[d+1] = q4.y; qr[d+2] = q4.z; qr[d+3] = q4.w;
    }
    float rinv = 1.0f / g_sum[(size_t)b*NN + n0 + pi];
    float* arow = attnp + ((size_t)b*NN + n0 + pi)*NN;
    const float* krow = g_k + ((size_t)b*CQ + sd)*NN + sj4;

    float cacc[8][4];
    #pragma unroll
    for (int nb = 0; nb < 8; nb++)
        #pragma unroll
        for (int q = 0; q < 4; q++) cacc[nb][q] = 0.f;

    int nblo = (pi >> 3) & 1, nbp = pi >> 4;

    // prestage K tile 0
    *(float4*)(smf + sd*TT + sj4) = *(const float4*)(krow + ct0*TT);

    for (int tt = 0; tt < nct; tt++) {
        int mt = ct0 + tt;
        int m0 = mt*TT;
        __syncthreads();                      // K(t) visible; P buffer free
        bool have = (tt + 1 < nct);
        float4 kreg;
        if (have) kreg = *(const float4*)(krow + m0 + TT);
        const float* ks = smf + (tt & 1)*1024;

        // ---- phase A: energy -> P; STG attention; P -> B frags ----
        unsigned long long eacc[8];
        #pragma unroll
        for (int p = 0; p < 8; p++) eacc[p] = 0ull;
        #pragma unroll
        for (int d = 0; d < CQ; d++) {
            unsigned long long qd = pack2(qr[d], qr[d]);
            const ulonglong2* kp = (const ulonglong2*)(ks + d*TT + pj0);
            ulonglong2 kA = kp[0], kB = kp[1], kC = kp[2], kD = kp[3];
            fma2(eacc[0], qd, kA.x); fma2(eacc[1], qd, kA.y);
            fma2(eacc[2], qd, kB.x); fma2(eacc[3], qd, kB.y);
            fma2(eacc[4], qd, kC.x); fma2(eacc[5], qd, kC.y);
            fma2(eacc[6], qd, kD.x); fma2(eacc[7], qd, kD.y);
        }
        float pv[16];
        #pragma unroll
        for (int p = 0; p < 8; p++) {
            float2 u = unpack2(eacc[p]);
            pv[2*p]   = __expf(u.x)*rinv;
            pv[2*p+1] = __expf(u.y)*rinv;
        }
        #pragma unroll
        for (int g = 0; g < 4; g++)
            *(float4*)(arow + m0 + pj0 + 4*g) =
                make_float4(pv[4*g], pv[4*g+1], pv[4*g+2], pv[4*g+3]);
        #pragma unroll
        for (int h = 0; h < 2; h++) {
            int ksv = ((t & 3) << 1) + h;
            #pragma unroll
            for (int j = 0; j < 4; j++) {
                int ls = ((pi & 7) << 2) + j;
                int s = (nbp + (ls >> 1)) & 3;
                uint2 u2;
                u2.x = f2tf32(pv[h*8 + j]);
                u2.y = f2tf32(pv[h*8 + j + 4]);
                *(uint2*)(bf + ksv*512 + ls*16 + s*4 + nblo*2) = u2;
            }
        }
        if (have)
            *(float4*)(smf + ((tt+1) & 1)*1024 + sd*TT + sj4) = kreg;
        __syncthreads();                      // P frags visible

        // ---- phase B: cacc += V . P^T via mma.sync tf32, V frags from gmem ----
        const uint4* vfp = g_vf + ((size_t)(b*64 + mt)*64 + w*8)*32 + lane;
        uint4 av[8];
        #pragma unroll
        for (int ksv = 0; ksv < 8; ksv++)
            av[ksv] = vfp[ksv*32];
        #pragma unroll
        for (int ksv = 0; ksv < 8; ksv++) {
            unsigned ar[4] = {av[ksv].x, av[ksv].y, av[ksv].z, av[ksv].w};
            #pragma unroll
            for (int np2 = 0; np2 < 4; np2++) {
                int s = (np2 + (lane >> 1)) & 3;
                uint4 bv = *(const uint4*)(bf + ksv*512 + lane*16 + s*4);
                mma_tf32(cacc[2*np2],     ar, bv.x, bv.y);
                mma_tf32(cacc[2*np2 + 1], ar, bv.z, bv.w);
            }
        }
    }

    // ---- epilogue: atomic out accumulation ----
    float gm = gamma[0];
    int rowc = lane >> 2, colb = (lane & 3) << 1;
    #pragma unroll
    for (int nb = 0; nb < 8; nb++) {
        int i = nb*8 + colb;
        size_t a0 = ((size_t)b*CC + w*16 + rowc)*NN + n0 + i;
        atomicAdd(outp + a0,            gm*cacc[nb][0]);
        atomicAdd(outp + a0 + 1,        gm*cacc[nb][1]);
        atomicAdd(outp + a0 + 8*NN,     gm*cacc[nb][2]);
        atomicAdd(outp + a0 + 8*NN + 1, gm*cacc[nb][3]);
    }
}

// ================= launch =================
extern "C" void kernel_launch(void* const* d_in, const int* in_sizes, int n_in,
                              void* d_out, int out_size)
{
    const float* x     = (const float*)d_in[0];
    const float* wq    = (const float*)d_in[1];
    const float* bq    = (const float*)d_in[2];
    const float* wk    = (const float*)d_in[3];
    const float* bk    = (const float*)d_in[4];
    const float* wv    = (const float*)d_in[5];
    const float* bv    = (const float*)d_in[6];
    const float* gamma = (const float*)d_in[7];

    float* outp  = (float*)d_out;
    float* attnp = outp + (size_t)BB*CC*NN;

    const int SM1 = (160*129 + 160) * 4;     // 83,200 B
    cudaFuncSetAttribute(qkv_kernel, cudaFuncAttributeMaxDynamicSharedMemorySize, SM1);

    qkv_kernel<<<BB*(NN/32), 256, SM1>>>(x, wq, bq, wk, bk, wv, bv, outp);
    sumexp_kernel<<<NCOMP + NVF, 256>>>();
    attn_kernel<<<NCOMP + NZERO, 256>>>(gamma, outp, attnp);
}

// round 7
// speedup vs baseline: 2.2245x; 1.1158x over previous
#include <cuda_runtime.h>

#define BB 4
#define CC 128
#define CQ 16
#define NN 4096
#define TT 64
#define CH 16
#define NCOMP 640
#define NZERO 1120
#define NVF 256

// ---------------- scratch ----------------
__device__ float g_q[(size_t)BB*NN*CQ];      // [b][n][d]
__device__ float g_k[(size_t)BB*CQ*NN];      // [b][d][n]
__device__ float g_v[(size_t)BB*CC*NN];      // [b][c][n]
__device__ float g_sum[(size_t)BB*NN];       // softmax denominators (atomic)
__device__ uint4 g_vf[(size_t)BB*64*2048];   // V tf32 A-fragments, 32KB per (b,mt)

// ---------------- helpers ----------------
static __device__ __forceinline__ unsigned long long pack2(float x, float y) {
    unsigned long long r;
    asm("mov.b64 %0, {%1, %2};" : "=l"(r) : "f"(x), "f"(y));
    return r;
}
static __device__ __forceinline__ void fma2(unsigned long long& d,
                                            unsigned long long a,
                                            unsigned long long b) {
    asm("fma.rn.f32x2 %0, %1, %2, %3;" : "=l"(d) : "l"(a), "l"(b), "l"(d));
}
static __device__ __forceinline__ float2 unpack2(unsigned long long v) {
    float x, y;
    asm("mov.b64 {%0, %1}, %2;" : "=f"(x), "=f"(y) : "l"(v));
    return make_float2(x, y);
}
static __device__ __forceinline__ unsigned f2tf32(float f) {
    unsigned r;
    asm("cvt.rn.tf32.f32 %0, %1;" : "=r"(r) : "f"(f));
    return r;
}
static __device__ __forceinline__ void mma_tf32(float c[4],
                                                const unsigned a[4],
                                                const unsigned b0, const unsigned b1) {
    asm volatile("mma.sync.aligned.m16n8k8.row.col.f32.tf32.tf32.f32 "
        "{%0,%1,%2,%3}, {%4,%5,%6,%7}, {%8,%9}, {%0,%1,%2,%3};"
        : "+f"(c[0]), "+f"(c[1]), "+f"(c[2]), "+f"(c[3])
        : "r"(a[0]), "r"(a[1]), "r"(a[2]), "r"(a[3]), "r"(b0), "r"(b1));
}
#define CP16(dst, src) \
    asm volatile("cp.async.cg.shared.global [%0], [%1], 16;" \
                 :: "r"(dst), "l"(src) : "memory")
#define CP_COMMIT() asm volatile("cp.async.commit_group;" ::: "memory")
#define CP_WAIT1()  asm volatile("cp.async.wait_group 1;" ::: "memory")
#define CP_WAIT0()  asm volatile("cp.async.wait_group 0;" ::: "memory")

// ================= kernel 1: q,k,v + out-init + g_sum zero =================
// 256 blocks: (b, 64-position tile). Weights [o][132] in smem (lane-contig o),
// x via cp.async double-buffered [128c x 32n] sub-tiles.
__global__ __launch_bounds__(256) void qkv_kernel(
    const float* __restrict__ x,
    const float* __restrict__ wq, const float* __restrict__ bq,
    const float* __restrict__ wk, const float* __restrict__ bk,
    const float* __restrict__ wv, const float* __restrict__ bv,
    float* __restrict__ outp)
{
    extern __shared__ float sm1[];
    float* ws = sm1;                 // [160][132]
    float* bs = ws + 160*132;        // [160]
    float* xs = bs + 160;            // 2 x [128][32]

    int bid = blockIdx.x;
    int b = bid & 3, tb = bid >> 2;
    int n0 = tb * 64;
    int t = threadIdx.x;
    int lane = t & 31;
    int j0 = (t >> 5) * 4;

    if (t < 64) g_sum[(size_t)b*NN + n0 + t] = 0.f;

    // kick off x sub-tile 0 copy
    unsigned xs_base;
    { unsigned long long g = (unsigned long long)__cvta_generic_to_shared(xs);
      xs_base = (unsigned)g; }
    const float* xsrc = x + (size_t)b*CC*NN + n0;
    {
        #pragma unroll
        for (int q = 0; q < 4; q++) {
            int idx = t + q*256;              // 0..1023
            int c = idx >> 3, f4 = (idx & 7) << 2;
            CP16(xs_base + (unsigned)((c*32 + f4) << 2),
                 (const void*)(xsrc + (size_t)c*NN + f4));
        }
        CP_COMMIT();
    }

    // stage weights (float4) + bias
    #pragma unroll
    for (int i = 0; i < 20; i++) {
        int idx = t + i*256;                  // 0..5119
        int o = idx >> 5, c4 = (idx & 31) << 2;
        const float* src;
        if (o < CQ)        src = wq + o*CC + c4;
        else if (o < 2*CQ) src = wk + (o-CQ)*CC + c4;
        else               src = wv + (o-2*CQ)*CC + c4;
        *(float4*)(ws + o*132 + c4) = *(const float4*)src;
    }
    if (t < 160) bs[t] = (t < CQ) ? bq[t] : (t < 2*CQ) ? bk[t-CQ] : bv[t-2*CQ];

    // out = x (pre-init for atomic accumulation)
    #pragma unroll
    for (int i = 0; i < 8; i++) {
        int idx = t + i*256;                  // 0..2047
        int c = idx >> 4, n4 = (idx & 15) << 2;
        size_t a = ((size_t)b*CC + c)*NN + n0 + n4;
        *(float4*)(outp + a) = *(const float4*)(x + a);
    }

    float bias[5];
    #pragma unroll
    for (int g = 0; g < 5; g++) bias[g] = bs[lane + 32*g];   // after staging: need sync first? bs written above by this block pre-sync; read after sync below

    #pragma unroll
    for (int st = 0; st < 2; st++) {
        if (st == 0) {
            #pragma unroll
            for (int q = 0; q < 4; q++) {
                int idx = t + q*256;
                int c = idx >> 3, f4 = (idx & 7) << 2;
                CP16(xs_base + (unsigned)((4096 + c*32 + f4) << 2),
                     (const void*)(xsrc + (size_t)c*NN + 32 + f4));
            }
            CP_COMMIT();
            CP_WAIT1();
        } else {
            CP_WAIT0();
        }
        __syncthreads();

        const float* xt = xs + st*4096;
        unsigned long long acc2[5][2];
        #pragma unroll
        for (int g = 0; g < 5; g++) { acc2[g][0] = 0ull; acc2[g][1] = 0ull; }

        #pragma unroll 4
        for (int c4 = 0; c4 < 32; c4++) {
            ulonglong2 xp[4];
            #pragma unroll
            for (int cc = 0; cc < 4; cc++)
                xp[cc] = *(const ulonglong2*)(xt + (c4*4 + cc)*32 + j0);
            #pragma unroll
            for (int g = 0; g < 5; g++) {
                float4 w4 = *(const float4*)(ws + (lane + 32*g)*132 + c4*4);
                unsigned long long wp;
                wp = pack2(w4.x, w4.x);
                fma2(acc2[g][0], wp, xp[0].x); fma2(acc2[g][1], wp, xp[0].y);
                wp = pack2(w4.y, w4.y);
                fma2(acc2[g][0], wp, xp[1].x); fma2(acc2[g][1], wp, xp[1].y);
                wp = pack2(w4.z, w4.z);
                fma2(acc2[g][0], wp, xp[2].x); fma2(acc2[g][1], wp, xp[2].y);
                wp = pack2(w4.w, w4.w);
                fma2(acc2[g][0], wp, xp[3].x); fma2(acc2[g][1], wp, xp[3].y);
            }
        }

        int nb = n0 + st*32 + j0;
        #pragma unroll
        for (int g = 0; g < 5; g++) {
            int o = lane + 32*g;
            float2 u0 = unpack2(acc2[g][0]);
            float2 u1 = unpack2(acc2[g][1]);
            float v0 = u0.x + bias[g], v1 = u0.y + bias[g];
            float v2 = u1.x + bias[g], v3 = u1.y + bias[g];
            if (o < CQ) {
                g_q[((size_t)b*NN + nb)*CQ + o]     = v0;
                g_q[((size_t)b*NN + nb + 1)*CQ + o] = v1;
                g_q[((size_t)b*NN + nb + 2)*CQ + o] = v2;
                g_q[((size_t)b*NN + nb + 3)*CQ + o] = v3;
            } else {
                float* row = (o < 2*CQ) ? (g_k + ((size_t)b*CQ + (o-CQ))*NN)
                                        : (g_v + ((size_t)b*CC + (o-2*CQ))*NN);
                *(float4*)(row + nb) = make_float4(v0, v1, v2, v3);
            }
        }
    }
}

// ================= kernel 2: chunked sum-exp + V-frag build ====
__global__ __launch_bounds__(256) void sumexp_kernel() {
    __shared__ float ksm[2*CQ*TT];
    int bid = blockIdx.x;
    int t = threadIdx.x;

    if (bid >= NCOMP) {                      // ---- V fragment build role ----
        int vb = bid - NCOMP;                // vb = b*64 + mt
        int b = vb >> 6;
        int mt = vb & 63;
        int ksv = t >> 5, lane = t & 31;
        int m = mt*64 + ksv*8 + (lane & 3);
        int cb = lane >> 2;
        const float* vp = g_v + (size_t)b*CC*NN;
        #pragma unroll
        for (int wc = 0; wc < 8; wc++) {
            int c = wc*16 + cb;
            uint4 u;
            u.x = f2tf32(vp[(size_t)c*NN + m]);
            u.y = f2tf32(vp[(size_t)(c+8)*NN + m]);
            u.z = f2tf32(vp[(size_t)c*NN + m + 4]);
            u.w = f2tf32(vp[(size_t)(c+8)*NN + m + 4]);
            g_vf[(size_t)vb*2048 + (wc*8 + ksv)*32 + lane] = u;
        }
        return;
    }

    int b = bid / 160, rem = bid % 160;
    int r = 0;
    for (; r < 64; r++) { int nc = 1 + (r>>4); if (rem < nc) break; rem -= nc; }
    int n0 = r*TT;
    int ct0 = rem*CH;
    int nct = min(CH, r + 1 - ct0);
    int pi = t >> 2, pj0 = (t & 3) << 4;
    int sd = t >> 4, sj4 = (t & 15) << 2;

    float qr[CQ];
    const float* qp = g_q + ((size_t)b*NN + n0 + pi)*CQ;
    #pragma unroll
    for (int d = 0; d < CQ; d += 4) {
        float4 q4 = *(const float4*)(qp + d);
        qr[d] = q4.x; qr[d+1] = q4.y; qr[d+2] = q4.z; qr[d+3] = q4.w;
    }
    const float* krow = g_k + ((size_t)b*CQ + sd)*NN + sj4;

    // prestage tile 0
    *(float4*)(ksm + sd*TT + sj4) = *(const float4*)(krow + ct0*TT);

    float ssum = 0.f;
    for (int tt = 0; tt < nct; tt++) {
        int m0 = (ct0 + tt)*TT;
        __syncthreads();
        bool have = (tt + 1 < nct);
        float4 kreg;
        if (have) kreg = *(const float4*)(krow + m0 + TT);
        const float* ks = ksm + (tt & 1)*1024;

        unsigned long long eacc[8];
        #pragma unroll
        for (int p = 0; p < 8; p++) eacc[p] = 0ull;
        #pragma unroll
        for (int d = 0; d < CQ; d++) {
            unsigned long long qd = pack2(qr[d], qr[d]);
            const ulonglong2* kp = (const ulonglong2*)(ks + d*TT + pj0);
            ulonglong2 kA = kp[0], kB = kp[1], kC = kp[2], kD = kp[3];
            fma2(eacc[0], qd, kA.x); fma2(eacc[1], qd, kA.y);
            fma2(eacc[2], qd, kB.x); fma2(eacc[3], qd, kB.y);
            fma2(eacc[4], qd, kC.x); fma2(eacc[5], qd, kC.y);
            fma2(eacc[6], qd, kD.x); fma2(eacc[7], qd, kD.y);
        }
        #pragma unroll
        for (int p = 0; p < 8; p++) {
            float2 u = unpack2(eacc[p]);
            ssum += __expf(u.x) + __expf(u.y);
        }
        if (have)
            *(float4*)(ksm + ((tt+1) & 1)*1024 + sd*TT + sj4) = kreg;
    }
    #pragma unroll
    for (int off = 1; off <= 2; off <<= 1)
        ssum += __shfl_xor_sync(0xffffffffu, ssum, off);
    if ((t & 3) == 0)
        atomicAdd(g_sum + (size_t)b*NN + n0 + pi, ssum);
}

// ================= kernel 3: attention write + HMMA tf32 PV (+zero blocks) ===
// dynamic smem: ksm 2x[16][64] (8KB) + P-frag [4096] (16KB) + V-frag 2x32KB
__global__ __launch_bounds__(256, 2) void attn_kernel(
    const float* __restrict__ gamma,
    float* __restrict__ outp, float* __restrict__ attnp)
{
    extern __shared__ float smf[];
    float* bf = smf + 2048;
    float* vf = smf + 6144;

    int bid = blockIdx.x;
    int t = threadIdx.x;

    if (bid >= NCOMP) {                       // ---- zero role ----
        int zi = bid - NCOMP;
        int b = zi / 280, rem = zi % 280;
        int ct = 1;
        for (; ct < 64; ct++) { int np = (ct + 7) >> 3; if (rem < np) break; rem -= np; }
        int r0 = rem * 512;
        int rend = min(r0 + 512, ct * 64);
        float4 z = make_float4(0.f, 0.f, 0.f, 0.f);
        size_t colo = (size_t)ct*64 + (size_t)(t & 15)*4;
        for (int row = r0 + (t >> 4); row < rend; row += 16)
            *(float4*)(attnp + ((size_t)b*NN + row)*NN + colo) = z;
        return;
    }

    int b = bid / 160, rem = bid % 160;
    int r = 0;
    for (; r < 64; r++) { int nc = 1 + (r>>4); if (rem < nc) break; rem -= nc; }
    int n0 = r*TT;
    int ct0 = rem*CH;
    int nct = min(CH, r + 1 - ct0);

    int lane = t & 31, w = t >> 5;
    int pi = t >> 2, pj0 = (t & 3) << 4;
    int sd = t >> 4, sj4 = (t & 15) << 2;

    unsigned vf_base;
    { unsigned long long g = (unsigned long long)__cvta_generic_to_shared(vf);
      vf_base = (unsigned)g; }

    float qr[CQ];
    const float* qp = g_q + ((size_t)b*NN + n0 + pi)*CQ;
    #pragma unroll
    for (int d = 0; d < CQ; d += 4) {
        float4 q4 = *(const float4*)(qp + d);
        qr[d] = q4.x; qr[d+1] = q4.y; qr[d+2] = q4.z; qr[d+3] = q4.w;
    }
    float rinv = 1.0f / g_sum[(size_t)b*NN + n0 + pi];
    float* arow = attnp + ((size_t)b*NN + n0 + pi)*NN;
    const float* krow = g_k + ((size_t)b*CQ + sd)*NN + sj4;
    const uint4* vtile0 = g_vf + (size_t)(b*64 + ct0)*2048;

    float cacc[8][4];
    #pragma unroll
    for (int nb = 0; nb < 8; nb++)
        #pragma unroll
        for (int q = 0; q < 4; q++) cacc[nb][q] = 0.f;

    int nblo = (pi >> 3) & 1, nbp = pi >> 4;

    // prestage K tile 0 + issue V tile 0 copy
    *(float4*)(smf + sd*TT + sj4) = *(const float4*)(krow + ct0*TT);
    {
        const uint4* src = vtile0 + t;
        unsigned dst = vf_base + (unsigned)(t << 4);
        #pragma unroll
        for (int q = 0; q < 8; q++)
            CP16(dst + q*4096, (const void*)(src + q*256));
        CP_COMMIT();
    }

    for (int tt = 0; tt < nct; tt++) {
        int mt = ct0 + tt;
        int m0 = mt*TT;
        bool have = (tt + 1 < nct);
        __syncthreads();                      // prev iter fully done; K(tt) visible
        if (have) {                           // V(tt+1) copy into other buffer
            const uint4* src = vtile0 + (size_t)(tt + 1)*2048 + t;
            unsigned dst = vf_base + (unsigned)(((tt + 1) & 1)*32768 + (t << 4));
            #pragma unroll
            for (int q = 0; q < 8; q++)
                CP16(dst + q*4096, (const void*)(src + q*256));
            CP_COMMIT();
        }
        float4 kreg;
        if (have) kreg = *(const float4*)(krow + m0 + TT);
        const float* ks = smf + (tt & 1)*1024;

        // ---- phase A: energy -> P; STG attention; P -> B frags ----
        unsigned long long eacc[8];
        #pragma unroll
        for (int p = 0; p < 8; p++) eacc[p] = 0ull;
        #pragma unroll
        for (int d = 0; d < CQ; d++) {
            unsigned long long qd = pack2(qr[d], qr[d]);
            const ulonglong2* kp = (const ulonglong2*)(ks + d*TT + pj0);
            ulonglong2 kA = kp[0], kB = kp[1], kC = kp[2], kD = kp[3];
            fma2(eacc[0], qd, kA.x); fma2(eacc[1], qd, kA.y);
            fma2(eacc[2], qd, kB.x); fma2(eacc[3], qd, kB.y);
            fma2(eacc[4], qd, kC.x); fma2(eacc[5], qd, kC.y);
            fma2(eacc[6], qd, kD.x); fma2(eacc[7], qd, kD.y);
        }
        float pv[16];
        #pragma unroll
        for (int p = 0; p < 8; p++) {
            float2 u = unpack2(eacc[p]);
            pv[2*p]   = __expf(u.x)*rinv;
            pv[2*p+1] = __expf(u.y)*rinv;
        }
        #pragma unroll
        for (int g = 0; g < 4; g++)
            *(float4*)(arow + m0 + pj0 + 4*g) =
                make_float4(pv[4*g], pv[4*g+1], pv[4*g+2], pv[4*g+3]);
        #pragma unroll
        for (int h = 0; h < 2; h++) {
            int ksv = ((t & 3) << 1) + h;
            #pragma unroll
            for (int j = 0; j < 4; j++) {
                int ls = ((pi & 7) << 2) + j;
                int s = (nbp + (ls >> 1)) & 3;
                uint2 u2;
                u2.x = f2tf32(pv[h*8 + j]);
                u2.y = f2tf32(pv[h*8 + j + 4]);
                *(uint2*)(bf + ksv*512 + ls*16 + s*4 + nblo*2) = u2;
            }
        }
        if (have) {
            *(float4*)(smf + ((tt+1) & 1)*1024 + sd*TT + sj4) = kreg;
            CP_WAIT1();                        // V(tt) complete (this thread)
        } else {
            CP_WAIT0();
        }
        __syncthreads();                      // P frags + everyone's V(tt) visible

        // ---- phase B: cacc += V . P^T via mma.sync tf32, V frags from smem ----
        const uint4* vsp = (const uint4*)(vf + (tt & 1)*8192) + w*8*32 + lane;
        uint4 av[8];
        #pragma unroll
        for (int ksv = 0; ksv < 8; ksv++)
            av[ksv] = vsp[ksv*32];
        #pragma unroll
        for (int ksv = 0; ksv < 8; ksv++) {
            unsigned ar[4] = {av[ksv].x, av[ksv].y, av[ksv].z, av[ksv].w};
            #pragma unroll
            for (int np2 = 0; np2 < 4; np2++) {
                int s = (np2 + (lane >> 1)) & 3;
                uint4 bv = *(const uint4*)(bf + ksv*512 + lane*16 + s*4);
                mma_tf32(cacc[2*np2],     ar, bv.x, bv.y);
                mma_tf32(cacc[2*np2 + 1], ar, bv.z, bv.w);
            }
        }
    }

    // ---- epilogue: atomic out accumulation ----
    float gm = gamma[0];
    int rowc = lane >> 2, colb = (lane & 3) << 1;
    #pragma unroll
    for (int nb = 0; nb < 8; nb++) {
        int i = nb*8 + colb;
        size_t a0 = ((size_t)b*CC + w*16 + rowc)*NN + n0 + i;
        atomicAdd(outp + a0,            gm*cacc[nb][0]);
        atomicAdd(outp + a0 + 1,        gm*cacc[nb][1]);
        atomicAdd(outp + a0 + 8*NN,     gm*cacc[nb][2]);
        atomicAdd(outp + a0 + 8*NN + 1, gm*cacc[nb][3]);
    }
}

// ================= launch =================
extern "C" void kernel_launch(void* const* d_in, const int* in_sizes, int n_in,
                              void* d_out, int out_size)
{
    const float* x     = (const float*)d_in[0];
    const float* wq    = (const float*)d_in[1];
    const float* bq    = (const float*)d_in[2];
    const float* wk    = (const float*)d_in[3];
    const float* bk    = (const float*)d_in[4];
    const float* wv    = (const float*)d_in[5];
    const float* bv    = (const float*)d_in[6];
    const float* gamma = (const float*)d_in[7];

    float* outp  = (float*)d_out;
    float* attnp = outp + (size_t)BB*CC*NN;

    const int SM1 = (160*132 + 160 + 2*4096) * 4;   // 117,888 B
    const int SM3 = (2048 + 4096 + 2*8192) * 4;     //  90,112 B
    cudaFuncSetAttribute(qkv_kernel,  cudaFuncAttributeMaxDynamicSharedMemorySize, SM1);
    cudaFuncSetAttribute(attn_kernel, cudaFuncAttributeMaxDynamicSharedMemorySize, SM3);

    qkv_kernel<<<BB*(NN/64), 256, SM1>>>(x, wq, bq, wk, bk, wv, bv, outp);
    sumexp_kernel<<<NCOMP + NVF, 256>>>();
    attn_kernel<<<NCOMP + NZERO, 256, SM3>>>(gamma, outp, attnp);
}

// round 12
// speedup vs baseline: 3.4623x; 1.5564x over previous
#include <cuda_runtime.h>

#define BB 4
#define CC 128
#define CQ 16
#define NN 4096
#define TT 64
#define CH 16
#define NCOMP 640
#define NZERO 1120
#define NVF 256

// ---------------- scratch ----------------
__device__ float g_q[(size_t)BB*NN*CQ];      // [b][n][d]
__device__ float g_k[(size_t)BB*CQ*NN];      // [b][d][n]
__device__ float g_v[(size_t)BB*CC*NN];      // [b][c][n]
__device__ float g_sum[(size_t)BB*NN];       // softmax denominators (atomic)
__device__ uint4 g_vf[(size_t)BB*64*2048];   // V tf32 A-fragments, 32KB per (b,mt)

// ---------------- helpers ----------------
static __device__ __forceinline__ unsigned long long pack2(float x, float y) {
    unsigned long long r;
    asm("mov.b64 %0, {%1, %2};" : "=l"(r) : "f"(x), "f"(y));
    return r;
}
static __device__ __forceinline__ void fma2(unsigned long long& d,
                                            unsigned long long a,
                                            unsigned long long b) {
    asm("fma.rn.f32x2 %0, %1, %2, %3;" : "=l"(d) : "l"(a), "l"(b), "l"(d));
}
static __device__ __forceinline__ float2 unpack2(unsigned long long v) {
    float x, y;
    asm("mov.b64 {%0, %1}, %2;" : "=f"(x), "=f"(y) : "l"(v));
    return make_float2(x, y);
}
static __device__ __forceinline__ unsigned f2tf32(float f) {
    unsigned r;
    asm("cvt.rn.tf32.f32 %0, %1;" : "=r"(r) : "f"(f));
    return r;
}
static __device__ __forceinline__ void mma_tf32(float c[4],
                                                const unsigned a[4],
                                                const unsigned b0, const unsigned b1) {
    asm volatile("mma.sync.aligned.m16n8k8.row.col.f32.tf32.tf32.f32 "
        "{%0,%1,%2,%3}, {%4,%5,%6,%7}, {%8,%9}, {%0,%1,%2,%3};"
        : "+f"(c[0]), "+f"(c[1]), "+f"(c[2]), "+f"(c[3])
        : "r"(a[0]), "r"(a[1]), "r"(a[2]), "r"(a[3]), "r"(b0), "r"(b1));
}
#define CP16(dst, src) \
    asm volatile("cp.async.cg.shared.global [%0], [%1], 16;" \
                 :: "r"(dst), "l"(src) : "memory")
#define CP_COMMIT() asm volatile("cp.async.commit_group;" ::: "memory")
#define CP_WAIT1()  asm volatile("cp.async.wait_group 1;" ::: "memory")
#define CP_WAIT0()  asm volatile("cp.async.wait_group 0;" ::: "memory")

// ================= kernel 1: q,k,v + out-init + g_sum zero =================
__global__ __launch_bounds__(256) void qkv_kernel(
    const float* __restrict__ x,
    const float* __restrict__ wq, const float* __restrict__ bq,
    const float* __restrict__ wk, const float* __restrict__ bk,
    const float* __restrict__ wv, const float* __restrict__ bv,
    float* __restrict__ outp)
{
    extern __shared__ float sm1[];
    float* ws = sm1;                 // [160][132]
    float* bs = ws + 160*132;        // [160]
    float* xs = bs + 160;            // 2 x [128][32]

    int bid = blockIdx.x;
    int b = bid & 3, tb = bid >> 2;
    int n0 = tb * 64;
    int t = threadIdx.x;
    int lane = t & 31;
    int j0 = (t >> 5) * 4;

    if (t < 64) g_sum[(size_t)b*NN + n0 + t] = 0.f;

    unsigned xs_base;
    { unsigned long long g = (unsigned long long)__cvta_generic_to_shared(xs);
      xs_base = (unsigned)g; }
    const float* xsrc = x + (size_t)b*CC*NN + n0;
    {
        #pragma unroll
        for (int q = 0; q < 4; q++) {
            int idx = t + q*256;
            int c = idx >> 3, f4 = (idx & 7) << 2;
            CP16(xs_base + (unsigned)((c*32 + f4) << 2),
                 (const void*)(xsrc + (size_t)c*NN + f4));
        }
        CP_COMMIT();
    }

    #pragma unroll
    for (int i = 0; i < 20; i++) {
        int idx = t + i*256;
        int o = idx >> 5, c4 = (idx & 31) << 2;
        const float* src;
        if (o < CQ)        src = wq + o*CC + c4;
        else if (o < 2*CQ) src = wk + (o-CQ)*CC + c4;
        else               src = wv + (o-2*CQ)*CC + c4;
        *(float4*)(ws + o*132 + c4) = *(const float4*)src;
    }
    if (t < 160) bs[t] = (t < CQ) ? bq[t] : (t < 2*CQ) ? bk[t-CQ] : bv[t-2*CQ];

    // out = x (pre-init for atomic accumulation)
    #pragma unroll
    for (int i = 0; i < 8; i++) {
        int idx = t + i*256;
        int c = idx >> 4, n4 = (idx & 15) << 2;
        size_t a = ((size_t)b*CC + c)*NN + n0 + n4;
        *(float4*)(outp + a) = *(const float4*)(x + a);
    }

    float bias[5];
    #pragma unroll
    for (int g = 0; g < 5; g++) bias[g] = bs[lane + 32*g];

    #pragma unroll
    for (int st = 0; st < 2; st++) {
        if (st == 0) {
            #pragma unroll
            for (int q = 0; q < 4; q++) {
                int idx = t + q*256;
                int c = idx >> 3, f4 = (idx & 7) << 2;
                CP16(xs_base + (unsigned)((4096 + c*32 + f4) << 2),
                     (const void*)(xsrc + (size_t)c*NN + 32 + f4));
            }
            CP_COMMIT();
            CP_WAIT1();
        } else {
            CP_WAIT0();
        }
        __syncthreads();

        const float* xt = xs + st*4096;
        unsigned long long acc2[5][2];
        #pragma unroll
        for (int g = 0; g < 5; g++) { acc2[g][0] = 0ull; acc2[g][1] = 0ull; }

        #pragma unroll 4
        for (int c4 = 0; c4 < 32; c4++) {
            ulonglong2 xp[4];
            #pragma unroll
            for (int cc = 0; cc < 4; cc++)
                xp[cc] = *(const ulonglong2*)(xt + (c4*4 + cc)*32 + j0);
            #pragma unroll
            for (int g = 0; g < 5; g++) {
                float4 w4 = *(const float4*)(ws + (lane + 32*g)*132 + c4*4);
                unsigned long long wp;
                wp = pack2(w4.x, w4.x);
                fma2(acc2[g][0], wp, xp[0].x); fma2(acc2[g][1], wp, xp[0].y);
                wp = pack2(w4.y, w4.y);
                fma2(acc2[g][0], wp, xp[1].x); fma2(acc2[g][1], wp, xp[1].y);
                wp = pack2(w4.z, w4.z);
                fma2(acc2[g][0], wp, xp[2].x); fma2(acc2[g][1], wp, xp[2].y);
                wp = pack2(w4.w, w4.w);
                fma2(acc2[g][0], wp, xp[3].x); fma2(acc2[g][1], wp, xp[3].y);
            }
        }

        int nb = n0 + st*32 + j0;
        #pragma unroll
        for (int g = 0; g < 5; g++) {
            int o = lane + 32*g;
            float2 u0 = unpack2(acc2[g][0]);
            float2 u1 = unpack2(acc2[g][1]);
            float v0 = u0.x + bias[g], v1 = u0.y + bias[g];
            float v2 = u1.x + bias[g], v3 = u1.y + bias[g];
            if (o < CQ) {
                g_q[((size_t)b*NN + nb)*CQ + o]     = v0;
                g_q[((size_t)b*NN + nb + 1)*CQ + o] = v1;
                g_q[((size_t)b*NN + nb + 2)*CQ + o] = v2;
                g_q[((size_t)b*NN + nb + 3)*CQ + o] = v3;
            } else {
                float* row = (o < 2*CQ) ? (g_k + ((size_t)b*CQ + (o-CQ))*NN)
                                        : (g_v + ((size_t)b*CC + (o-2*CQ))*NN);
                *(float4*)(row + nb) = make_float4(v0, v1, v2, v3);
            }
        }
    }
}

// ================= kernel 2: chunked sum-exp (2-row phase A) + V-frag build =
__global__ __launch_bounds__(256) void sumexp_kernel() {
    __shared__ float ksm[2*CQ*TT];
    int bid = blockIdx.x;
    int t = threadIdx.x;

    if (bid >= NCOMP) {                      // ---- V fragment build role ----
        int vb = bid - NCOMP;                // vb = b*64 + mt
        int b = vb >> 6;
        int mt = vb & 63;
        int ksv = t >> 5, lane = t & 31;
        int m = mt*64 + ksv*8 + (lane & 3);
        int cb = lane >> 2;
        const float* vp = g_v + (size_t)b*CC*NN;
        #pragma unroll
        for (int wc = 0; wc < 8; wc++) {
            int c = wc*16 + cb;
            uint4 u;
            u.x = f2tf32(vp[(size_t)c*NN + m]);
            u.y = f2tf32(vp[(size_t)(c+8)*NN + m]);
            u.z = f2tf32(vp[(size_t)c*NN + m + 4]);
            u.w = f2tf32(vp[(size_t)(c+8)*NN + m + 4]);
            g_vf[(size_t)vb*2048 + (wc*8 + ksv)*32 + lane] = u;
        }
        return;
    }

    int b = bid / 160, rem = bid % 160;
    int r = 0;
    for (; r < 64; r++) { int nc = 1 + (r>>4); if (rem < nc) break; rem -= nc; }
    int n0 = r*TT;
    int ct0 = rem*CH;
    int nct = min(CH, r + 1 - ct0);
    int pi2 = t >> 3, pj0 = (t & 7) << 3;    // rows (pi2, pi2+32), 8 cols
    int sd = t >> 4, sj4 = (t & 15) << 2;

    float qlo[CQ], qhi[CQ];
    const float* qpl = g_q + ((size_t)b*NN + n0 + pi2)*CQ;
    const float* qph = qpl + 32*CQ;
    #pragma unroll
    for (int d = 0; d < CQ; d += 4) {
        float4 a = *(const float4*)(qpl + d);
        qlo[d] = a.x; qlo[d+1] = a.y; qlo[d+2] = a.z; qlo[d+3] = a.w;
        float4 h = *(const float4*)(qph + d);
        qhi[d] = h.x; qhi[d+1] = h.y; qhi[d+2] = h.z; qhi[d+3] = h.w;
    }
    const float* krow = g_k + ((size_t)b*CQ + sd)*NN + sj4;

    // prestage tile 0
    *(float4*)(ksm + sd*TT + sj4) = *(const float4*)(krow + ct0*TT);

    float slo = 0.f, shi = 0.f;
    for (int tt = 0; tt < nct; tt++) {
        int m0 = (ct0 + tt)*TT;
        __syncthreads();
        bool have = (tt + 1 < nct);
        float4 kreg;
        if (have) kreg = *(const float4*)(krow + m0 + TT);
        const float* ks = ksm + (tt & 1)*1024;

        unsigned long long elo[4], ehi[4];
        #pragma unroll
        for (int p = 0; p < 4; p++) { elo[p] = 0ull; ehi[p] = 0ull; }
        #pragma unroll
        for (int d = 0; d < CQ; d++) {
            const ulonglong2* kp = (const ulonglong2*)(ks + d*TT + pj0);
            ulonglong2 kA = kp[0], kB = kp[1];
            unsigned long long qdl = pack2(qlo[d], qlo[d]);
            unsigned long long qdh = pack2(qhi[d], qhi[d]);
            fma2(elo[0], qdl, kA.x); fma2(elo[1], qdl, kA.y);
            fma2(elo[2], qdl, kB.x); fma2(elo[3], qdl, kB.y);
            fma2(ehi[0], qdh, kA.x); fma2(ehi[1], qdh, kA.y);
            fma2(ehi[2], qdh, kB.x); fma2(ehi[3], qdh, kB.y);
        }
        #pragma unroll
        for (int p = 0; p < 4; p++) {
            float2 ul = unpack2(elo[p]);
            slo += __expf(ul.x) + __expf(ul.y);
            float2 uh = unpack2(ehi[p]);
            shi += __expf(uh.x) + __expf(uh.y);
        }
        if (have)
            *(float4*)(ksm + ((tt+1) & 1)*1024 + sd*TT + sj4) = kreg;
    }
    #pragma unroll
    for (int off = 1; off <= 4; off <<= 1) {
        slo += __shfl_xor_sync(0xffffffffu, slo, off);
        shi += __shfl_xor_sync(0xffffffffu, shi, off);
    }
    if ((t & 7) == 0) {
        atomicAdd(g_sum + (size_t)b*NN + n0 + pi2,      slo);
        atomicAdd(g_sum + (size_t)b*NN + n0 + pi2 + 32, shi);
    }
}

// ================= kernel 3: attention write + HMMA tf32 PV (+zero blocks) ===
__global__ __launch_bounds__(256, 2) void attn_kernel(
    const float* __restrict__ gamma,
    float* __restrict__ outp, float* __restrict__ attnp)
{
    extern __shared__ float smf[];
    float* bf = smf + 2048;
    float* vf = smf + 6144;

    int bid = blockIdx.x;
    int t = threadIdx.x;

    if (bid >= NCOMP) {                       // ---- zero role ----
        int zi = bid - NCOMP;
        int b = zi / 280, rem = zi % 280;
        int ct = 1;
        for (; ct < 64; ct++) { int np = (ct + 7) >> 3; if (rem < np) break; rem -= np; }
        int r0 = rem * 512;
        int rend = min(r0 + 512, ct * 64);
        float4 z = make_float4(0.f, 0.f, 0.f, 0.f);
        size_t colo = (size_t)ct*64 + (size_t)(t & 15)*4;
        for (int row = r0 + (t >> 4); row < rend; row += 16)
            *(float4*)(attnp + ((size_t)b*NN + row)*NN + colo) = z;
        return;
    }

    int b = bid / 160, rem = bid % 160;
    int r = 0;
    for (; r < 64; r++) { int nc = 1 + (r>>4); if (rem < nc) break; rem -= nc; }
    int n0 = r*TT;
    int ct0 = rem*CH;
    int nct = min(CH, r + 1 - ct0);

    int lane = t & 31, w = t >> 5;
    int pi2 = t >> 3, pj0 = (t & 7) << 3;    // rows (pi2, pi2+32), 8 cols
    int ksv = t & 7;                          // this thread owns m-group ksv
    int sd = t >> 4, sj4 = (t & 15) << 2;

    unsigned vf_base;
    { unsigned long long g = (unsigned long long)__cvta_generic_to_shared(vf);
      vf_base = (unsigned)g; }

    float qlo[CQ], qhi[CQ];
    const float* qpl = g_q + ((size_t)b*NN + n0 + pi2)*CQ;
    const float* qph = qpl + 32*CQ;
    #pragma unroll
    for (int d = 0; d < CQ; d += 4) {
        float4 a = *(const float4*)(qpl + d);
        qlo[d] = a.x; qlo[d+1] = a.y; qlo[d+2] = a.z; qlo[d+3] = a.w;
        float4 h = *(const float4*)(qph + d);
        qhi[d] = h.x; qhi[d+1] = h.y; qhi[d+2] = h.z; qhi[d+3] = h.w;
    }
    float rinv_lo = 1.0f / g_sum[(size_t)b*NN + n0 + pi2];
    float rinv_hi = 1.0f / g_sum[(size_t)b*NN + n0 + pi2 + 32];
    float* arow_lo = attnp + ((size_t)b*NN + n0 + pi2)*NN;
    float* arow_hi = arow_lo + (size_t)32*NN;
    const float* krow = g_k + ((size_t)b*CQ + sd)*NN + sj4;
    const uint4* vtile0 = g_vf + (size_t)(b*64 + ct0)*2048;

    float cacc[8][4];
    #pragma unroll
    for (int nb = 0; nb < 8; nb++)
        #pragma unroll
        for (int q = 0; q < 4; q++) cacc[nb][q] = 0.f;

    // B-frag write constants for the two rows
    int lsb_lo = (pi2 & 7) << 2, nbp_lo = pi2 >> 4, nblo_lo = (pi2 >> 3) & 1;
    int rh = pi2 + 32;
    int lsb_hi = (rh & 7) << 2,  nbp_hi = rh >> 4,  nblo_hi = (rh >> 3) & 1;

    // prestage K tile 0 + issue V tile 0 copy
    *(float4*)(smf + sd*TT + sj4) = *(const float4*)(krow + ct0*TT);
    {
        const uint4* src = vtile0 + t;
        unsigned dst = vf_base + (unsigned)(t << 4);
        #pragma unroll
        for (int q = 0; q < 8; q++)
            CP16(dst + q*4096, (const void*)(src + q*256));
        CP_COMMIT();
    }

    for (int tt = 0; tt < nct; tt++) {
        int m0 = (ct0 + tt)*TT;
        bool have = (tt + 1 < nct);
        __syncthreads();
        if (have) {
            const uint4* src = vtile0 + (size_t)(tt + 1)*2048 + t;
            unsigned dst = vf_base + (unsigned)(((tt + 1) & 1)*32768 + (t << 4));
            #pragma unroll
            for (int q = 0; q < 8; q++)
                CP16(dst + q*4096, (const void*)(src + q*256));
            CP_COMMIT();
        }
        float4 kreg;
        if (have) kreg = *(const float4*)(krow + m0 + TT);
        const float* ks = smf + (tt & 1)*1024;

        // ---- phase A: energy (2 rows x 8 cols) -> p; STG; B frags ----
        unsigned long long elo[4], ehi[4];
        #pragma unroll
        for (int p = 0; p < 4; p++) { elo[p] = 0ull; ehi[p] = 0ull; }
        #pragma unroll
        for (int d = 0; d < CQ; d++) {
            const ulonglong2* kp = (const ulonglong2*)(ks + d*TT + pj0);
            ulonglong2 kA = kp[0], kB = kp[1];
            unsigned long long qdl = pack2(qlo[d], qlo[d]);
            unsigned long long qdh = pack2(qhi[d], qhi[d]);
            fma2(elo[0], qdl, kA.x); fma2(elo[1], qdl, kA.y);
            fma2(elo[2], qdl, kB.x); fma2(elo[3], qdl, kB.y);
            fma2(ehi[0], qdh, kA.x); fma2(ehi[1], qdh, kA.y);
            fma2(ehi[2], qdh, kB.x); fma2(ehi[3], qdh, kB.y);
        }
        float pvl[8], pvh[8];
        #pragma unroll
        for (int p = 0; p < 4; p++) {
            float2 ul = unpack2(elo[p]);
            pvl[2*p]   = __expf(ul.x)*rinv_lo;
            pvl[2*p+1] = __expf(ul.y)*rinv_lo;
            float2 uh = unpack2(ehi[p]);
            pvh[2*p]   = __expf(uh.x)*rinv_hi;
            pvh[2*p+1] = __expf(uh.y)*rinv_hi;
        }
        *(float4*)(arow_lo + m0 + pj0)     = make_float4(pvl[0], pvl[1], pvl[2], pvl[3]);
        *(float4*)(arow_lo + m0 + pj0 + 4) = make_float4(pvl[4], pvl[5], pvl[6], pvl[7]);
        *(float4*)(arow_hi + m0 + pj0)     = make_float4(pvh[0], pvh[1], pvh[2], pvh[3]);
        *(float4*)(arow_hi + m0 + pj0 + 4) = make_float4(pvh[4], pvh[5], pvh[6], pvh[7]);
        #pragma unroll
        for (int j = 0; j < 4; j++) {
            int ls = lsb_lo + j;
            int s = (nbp_lo + (ls >> 1) + ksv) & 3;
            uint2 u2;
            u2.x = f2tf32(pvl[j]);
            u2.y = f2tf32(pvl[j + 4]);
            *(uint2*)(bf + ksv*512 + ls*16 + s*4 + nblo_lo*2) = u2;
        }
        #pragma unroll
        for (int j = 0; j < 4; j++) {
            int ls = lsb_hi + j;
            int s = (nbp_hi + (ls >> 1) + ksv) & 3;
            uint2 u2;
            u2.x = f2tf32(pvh[j]);
            u2.y = f2tf32(pvh[j + 4]);
            *(uint2*)(bf + ksv*512 + ls*16 + s*4 + nblo_hi*2) = u2;
        }
        if (have) {
            *(float4*)(smf + ((tt+1) & 1)*1024 + sd*TT + sj4) = kreg;
            CP_WAIT1();
        } else {
            CP_WAIT0();
        }
        __syncthreads();

        // ---- phase B: cacc += V . P^T via mma.sync tf32, V frags from smem ----
        const uint4* vsp = (const uint4*)(vf + (tt & 1)*8192) + w*8*32 + lane;
        #pragma unroll
        for (int kv = 0; kv < 8; kv++) {
            uint4 a = vsp[kv*32];
            unsigned ar[4] = {a.x, a.y, a.z, a.w};
            #pragma unroll
            for (int np2 = 0; np2 < 4; np2++) {
                int s = (np2 + (lane >> 1) + kv) & 3;
                uint4 bv = *(const uint4*)(bf + kv*512 + lane*16 + s*4);
                mma_tf32(cacc[2*np2],     ar, bv.x, bv.y);
                mma_tf32(cacc[2*np2 + 1], ar, bv.z, bv.w);
            }
        }
    }

    // ---- epilogue: atomic out accumulation ----
    float gm = gamma[0];
    int rowc = lane >> 2, colb = (lane & 3) << 1;
    #pragma unroll
    for (int nb = 0; nb < 8; nb++) {
        int i = nb*8 + colb;
        size_t a0 = ((size_t)b*CC + w*16 + rowc)*NN + n0 + i;
        atomicAdd(outp + a0,            gm*cacc[nb][0]);
        atomicAdd(outp + a0 + 1,        gm*cacc[nb][1]);
        atomicAdd(outp + a0 + 8*NN,     gm*cacc[nb][2]);
        atomicAdd(outp + a0 + 8*NN + 1, gm*cacc[nb][3]);
    }
}

// ================= launch =================
extern "C" void kernel_launch(void* const* d_in, const int* in_sizes, int n_in,
                              void* d_out, int out_size)
{
    const float* x     = (const float*)d_in[0];
    const float* wq    = (const float*)d_in[1];
    const float* bq    = (const float*)d_in[2];
    const float* wk    = (const float*)d_in[3];
    const float* bk    = (const float*)d_in[4];
    const float* wv    = (const float*)d_in[5];
    const float* bv    = (const float*)d_in[6];
    const float* gamma = (const float*)d_in[7];

    float* outp  = (float*)d_out;
    float* attnp = outp + (size_t)BB*CC*NN;

    const int SM1 = (160*132 + 160 + 2*4096) * 4;   // 117,888 B
    const int SM3 = (2048 + 4096 + 2*8192) * 4;     //  90,112 B
    cudaFuncSetAttribute(qkv_kernel,  cudaFuncAttributeMaxDynamicSharedMemorySize, SM1);
    cudaFuncSetAttribute(attn_kernel, cudaFuncAttributeMaxDynamicSharedMemorySize, SM3);

    qkv_kernel<<<BB*(NN/64), 256, SM1>>>(x, wq, bq, wk, bk, wv, bv, outp);
    sumexp_kernel<<<NCOMP + NVF, 256>>>();
    attn_kernel<<<NCOMP + NZERO, 256, SM3>>>(gamma, outp, attnp);
}